// round 16
// baseline (speedup 1.0000x reference)
#include <cuda_runtime.h>
#include <cuda_bf16.h>
#include <math.h>
#include <stdint.h>

#define N_TOT 512
#define D_DIM 512

__device__ __align__(16) float g_LO[N_TOT * N_TOT];   // lo = -dist/2
__device__ __align__(16) float g_ys[N_TOT];           // labels sorted ascending
__device__ __align__(16) int   g_perm[N_TOT];         // g_ys[m] = y[g_perm[m]]
__device__ __align__(16) uint4 g_Fhi[N_TOT * 64];     // bf16 hi of F (row-major)
__device__ __align__(16) uint4 g_Flo[N_TOT * 64];     // bf16 lo of F
__device__ __align__(16) float g_norm[N_TOT];
__device__ unsigned g_ccnt;                           // monotonic conversion barrier
__device__ double g_acc;
__device__ int    g_count;

__device__ __forceinline__ const float* frow(const float* wt, const float* mt, int r) {
    return (r < 256) ? (wt + r * D_DIM) : (mt + (r - 256) * D_DIM);
}
__device__ __forceinline__ float lab(const float* lw, const float* lm, int r) {
    return (r < 256) ? lw[r] : lm[r - 256];
}

// ===================== warp-MMA helpers (HMMA bf16) =====================
__device__ __forceinline__ uint32_t smem_u32(const void* p) {
    uint32_t a;
    asm("{ .reg .u64 t; cvta.to.shared.u64 t, %1; cvt.u32.u64 %0, t; }" : "=r"(a) : "l"(p));
    return a;
}
__device__ __forceinline__ void ldsm4(uint32_t* r, uint32_t addr) {
    asm volatile("ldmatrix.sync.aligned.m8n8.x4.shared.b16 {%0,%1,%2,%3}, [%4];"
                 : "=r"(r[0]), "=r"(r[1]), "=r"(r[2]), "=r"(r[3]) : "r"(addr));
}
__device__ __forceinline__ void mma_bf16(float* c, const uint32_t* a, const uint32_t* b) {
    asm volatile("mma.sync.aligned.m16n8k16.row.col.f32.bf16.bf16.f32 "
                 "{%0,%1,%2,%3}, {%4,%5,%6,%7}, {%8,%9}, {%0,%1,%2,%3};"
                 : "+f"(c[0]), "+f"(c[1]), "+f"(c[2]), "+f"(c[3])
                 : "r"(a[0]), "r"(a[1]), "r"(a[2]), "r"(a[3]), "r"(b[0]), "r"(b[1]));
}
__device__ __forceinline__ void split4(float4 f, uint2& h, uint2& l) {
    __nv_bfloat162 h0 = __floats2bfloat162_rn(f.x, f.y);
    __nv_bfloat162 h1 = __floats2bfloat162_rn(f.z, f.w);
    float2 g0 = __bfloat1622float2(h0), g1 = __bfloat1622float2(h1);
    __nv_bfloat162 l0 = __floats2bfloat162_rn(f.x - g0.x, f.y - g0.y);
    __nv_bfloat162 l1 = __floats2bfloat162_rn(f.z - g1.x, f.w - g1.y);
    h = make_uint2(*(uint32_t*)&h0, *(uint32_t*)&h1);
    l = make_uint2(*(uint32_t*)&l0, *(uint32_t*)&l1);
}

#define STRIDE 40          // bf16 elems per smem row (80B pitch, 16B-aligned)
#define NCHUNK 16          // 16 chunks of 32 fp32-k
#define NBUF 3
#define NTILES 136         // 16*17/2 upper-triangle 32x32 tiles
#define GRID_G (NTILES + 4)

struct GemmSmem {
    float nw[8];
    union {
        unsigned short buf[4][NBUF][32 * STRIDE];   // a_hi, a_lo, b_hi, b_lo
        float stage[32][33];
        float ls[N_TOT];
    } u;
};

// ---------------------------------------------------------------------------
// Kernel 1: 136 tile blocks (distributed convert -> grid barrier -> light
// bf16 HMMA mainloop -> epilogue+mirror) + 4 sort blocks. 256 threads.
// ---------------------------------------------------------------------------
__global__ void __launch_bounds__(256)
gemm_sort_kernel(const float* __restrict__ wt, const float* __restrict__ mt,
                 const float* __restrict__ lw, const float* __restrict__ lm) {
    __shared__ GemmSmem sm;

    const int t = threadIdx.x;
    const int bid = blockIdx.x;
    const int w = t >> 5, lane = t & 31;

    if (bid < NTILES) {
        // ---------- phase 1: distributed conversion (bids 0..127: 4 rows) ---
        if (bid < 128) {
            const int cr = t >> 6;              // 0..3 row within group
            const int row = bid * 4 + cr;
            const int idx = t & 63;             // 64 threads per row
            const float4* rp4 = (const float4*)frow(wt, mt, row);
            float4 f0 = rp4[idx * 2];
            float4 f1 = rp4[idx * 2 + 1];
            float nrm = f0.x*f0.x + f0.y*f0.y + f0.z*f0.z + f0.w*f0.w
                      + f1.x*f1.x + f1.y*f1.y + f1.z*f1.z + f1.w*f1.w;
            uint2 h0, l0, h1, l1;
            split4(f0, h0, l0);
            split4(f1, h1, l1);
            g_Fhi[row * 64 + idx] = make_uint4(h0.x, h0.y, h1.x, h1.y);
            g_Flo[row * 64 + idx] = make_uint4(l0.x, l0.y, l1.x, l1.y);
            #pragma unroll
            for (int o = 16; o; o >>= 1) nrm += __shfl_xor_sync(0xffffffffu, nrm, o);
            if (lane == 0) sm.nw[w] = nrm;
            __syncthreads();
            if (t < 4) g_norm[bid * 4 + t] = sm.nw[2 * t] + sm.nw[2 * t + 1];
        }

        // ---------- grid barrier over the 136 tile blocks (monotonic) -------
        __syncthreads();
        if (t == 0) {
            __threadfence();
            unsigned ticket = atomicAdd(&g_ccnt, 1u);
            unsigned target = (ticket / (unsigned)NTILES + 1u) * (unsigned)NTILES;
            while (atomicAdd(&g_ccnt, 0u) < target) {}
            __threadfence();
        }
        __syncthreads();

        // ---------- phase 2: tile MMA ---------------------------------------
        int ti = 0, base = 0;
        while (base + (16 - ti) <= bid) { base += 16 - ti; ti++; }
        const int tj = ti + (bid - base);
        const int I = ti * 32, J = tj * 32;

        // load roles: t<128 -> A arrays, t>=128 -> B arrays; 1 uint4 hi + lo each
        const int half = t >> 7;
        const int rr = (t & 127) >> 2;          // row 0..31
        const int qq = t & 3;                   // uint4 quad within chunk
        const int R = ((half ? J : I) + rr) * 64 + qq;
        const int hiArr = half * 2, loArr = hiArr + 1;
        const uint32_t sts_off = (uint32_t)(rr * STRIDE + qq * 8);   // elems

        const int wm = w >> 2, wn = w & 3;
        float c[4] = {};
        const uint32_t a_hi_b = smem_u32(sm.u.buf[0][0]);
        const uint32_t a_lo_b = smem_u32(sm.u.buf[1][0]);
        const uint32_t b_hi_b = smem_u32(sm.u.buf[2][0]);
        const uint32_t b_lo_b = smem_u32(sm.u.buf[3][0]);
        const uint32_t step = 32 * STRIDE * 2;  // bytes between buffers

        const uint32_t a_off = (uint32_t)((wm * 16 + (lane & 15)) * (STRIDE * 2) + ((lane >> 4) & 1) * 16);
        const uint32_t b_off = (uint32_t)((wn * 8 + (lane & 7)) * (STRIDE * 2) + (lane >> 3) * 16);

        uint4 vh, vl;
        // prologue: chunk0 load+store, chunk1 prefetch
        vh = g_Fhi[R]; vl = g_Flo[R];
        *(uint4*)&sm.u.buf[hiArr][0][sts_off] = vh;
        *(uint4*)&sm.u.buf[loArr][0][sts_off] = vl;
        vh = g_Fhi[R + 4]; vl = g_Flo[R + 4];

        for (int n = 0; n < NCHUNK; n++) {
            const int cur = n % NBUF;
            if (n + 1 < NCHUNK) {
                const int nxt = (n + 1) % NBUF;
                *(uint4*)&sm.u.buf[hiArr][nxt][sts_off] = vh;
                *(uint4*)&sm.u.buf[loArr][nxt][sts_off] = vl;
            }
            if (n + 2 < NCHUNK) {
                vh = g_Fhi[R + (n + 2) * 4];
                vl = g_Flo[R + (n + 2) * 4];
            }
            __syncthreads();

            uint32_t Bh[4], Bl[4];
            ldsm4(Bh, b_hi_b + cur * step + b_off);
            ldsm4(Bl, b_lo_b + cur * step + b_off);
            #pragma unroll
            for (int ks = 0; ks < 2; ks++) {
                uint32_t Ah[4], Al[4];
                ldsm4(Ah, a_hi_b + cur * step + a_off + ks * 32);
                ldsm4(Al, a_lo_b + cur * step + a_off + ks * 32);
                mma_bf16(c, Ah, Bh + ks * 2);
                mma_bf16(c, Ah, Bl + ks * 2);
                mma_bf16(c, Al, Bh + ks * 2);
            }
        }
        __syncthreads();   // all ldsm reads done -> stage overlay safe

        const int r0 = wm * 16 + (lane >> 2);
        const int cL = wn * 8 + (lane & 3) * 2;
        const float ni0 = g_norm[I + r0], ni1 = g_norm[I + r0 + 8];
        const float nj0 = g_norm[J + cL], nj1 = g_norm[J + cL + 1];
        float sq, v00, v01, v10, v11;
        sq = fmaf(-2.f, c[0], ni0 + nj0); v00 = -0.5f * sqrtf(fmaxf(sq, 0.f));
        sq = fmaf(-2.f, c[1], ni0 + nj1); v01 = -0.5f * sqrtf(fmaxf(sq, 0.f));
        sq = fmaf(-2.f, c[2], ni1 + nj0); v10 = -0.5f * sqrtf(fmaxf(sq, 0.f));
        sq = fmaf(-2.f, c[3], ni1 + nj1); v11 = -0.5f * sqrtf(fmaxf(sq, 0.f));
        *(float2*)&g_LO[(I + r0) * N_TOT + J + cL]     = make_float2(v00, v01);
        *(float2*)&g_LO[(I + r0 + 8) * N_TOT + J + cL] = make_float2(v10, v11);

        if (ti != tj) {
            sm.u.stage[r0][cL] = v00;     sm.u.stage[r0][cL + 1] = v01;
            sm.u.stage[r0 + 8][cL] = v10; sm.u.stage[r0 + 8][cL + 1] = v11;
            __syncthreads();
            const int mc = t >> 3;
            const int rg = (t & 7) * 4;
            float4 o;
            o.x = sm.u.stage[rg + 0][mc]; o.y = sm.u.stage[rg + 1][mc];
            o.z = sm.u.stage[rg + 2][mc]; o.w = sm.u.stage[rg + 3][mc];
            *(float4*)&g_LO[(J + mc) * N_TOT + I + rg] = o;
        }
    } else {
        // ---- 4 sort blocks (2 threads/element); resets accumulators ----
        const int sb = bid - NTILES;
        if (sb == 0 && t == 0) { g_acc = 0.0; g_count = 0; }
        float* ls = sm.u.ls;
        for (int m = t; m < N_TOT; m += 256) ls[m] = lab(lw, lm, m);
        __syncthreads();
        const int e = sb * 128 + (t >> 1);
        const int half = t & 1;
        const float ye = ls[e];
        int rank = 0;
        const float4* L4 = (const float4*)ls + half * 64;
        const int jbase = half * 256;
        #pragma unroll 4
        for (int j4 = 0; j4 < 64; j4++) {
            float4 v = L4[j4];
            int j = jbase + j4 * 4;
            rank += (v.x < ye) || (v.x == ye && (j + 0) < e);
            rank += (v.y < ye) || (v.y == ye && (j + 1) < e);
            rank += (v.z < ye) || (v.z == ye && (j + 2) < e);
            rank += (v.w < ye) || (v.w == ye && (j + 3) < e);
        }
        rank += __shfl_xor_sync(0xffffffffu, rank, 1);
        if (half == 0) { g_ys[rank] = ye; g_perm[rank] = e; }
    }
}

// ---------------------------------------------------------------------------
// Kernel 2: per-row loss — VERBATIM champion numerics
// ---------------------------------------------------------------------------
__global__ void __launch_bounds__(N_TOT)
loss_kernel(const float* __restrict__ lw, const float* __restrict__ lm,
            float* __restrict__ out) {
    __shared__ float sLO[N_TOT];
    __shared__ float sY[N_TOT];
    __shared__ float sD[N_TOT];
    __shared__ float sP[N_TOT + 1];
    __shared__ float warpS[16];
    __shared__ int   sp, spos;

    const int i = blockIdx.x;
    const int m = threadIdx.x;
    const int lane = m & 31, w = m >> 5;

    sLO[m] = g_LO[i * N_TOT + m];
    sY[m]  = g_ys[m];
    const int pm = g_perm[m];
    const float yi = lab(lw, lm, i);
    if (pm == i) spos = m;
    __syncthreads();

    const float tm = fabsf(yi - sY[m]);
    sD[m] = tm;
    if (m == 0) {
        int lo_ = 0, hi_ = N_TOT;
        while (lo_ < hi_) { int mid = (lo_ + hi_) >> 1; if (sY[mid] >= yi) hi_ = mid; else lo_ = mid + 1; }
        sp = lo_;
    }

    const float lo_s = sLO[pm];
    const float e = (pm == i) ? 0.f : __expf(lo_s);

    float v = e;
    #pragma unroll
    for (int o = 1; o < 32; o <<= 1) {
        float nvl = __shfl_up_sync(0xffffffffu, v, o);
        if (lane >= o) v += nvl;
    }
    if (lane == 31) warpS[w] = v;
    __syncthreads();
    if (w == 0) {
        float s = (lane < 16) ? warpS[lane] : 0.f;
        #pragma unroll
        for (int o = 1; o < 16; o <<= 1) {
            float nvl = __shfl_up_sync(0xffffffffu, s, o);
            if (lane >= o) s += nvl;
        }
        if (lane < 16) warpS[lane] = s;
    }
    __syncthreads();
    const float off = (w > 0) ? warpS[w - 1] : 0.f;
    const float S = warpS[15];
    sP[m] = off + v - e;
    if (m == N_TOT - 1) sP[N_TOT] = off + v;
    __syncthreads();

    const int p = sp;
    int a, b;
    if (m < p) {
        int j = m + 1;
        while (j < p && sD[j] == tm) j++;
        a = j;
        int lo_ = p, hi_ = N_TOT;
        while (lo_ < hi_) { int mid = (lo_ + hi_) >> 1; if (sD[mid] >= tm) hi_ = mid; else lo_ = mid + 1; }
        b = lo_;
    } else {
        int j = m;
        while (j > p && sD[j - 1] == tm) j--;
        b = j;
        int lo_ = 0, hi_ = p;
        while (lo_ < hi_) { int mid = (lo_ + hi_) >> 1; if (sD[mid] < tm) hi_ = mid; else lo_ = mid + 1; }
        a = lo_;
    }

    const float denom = sP[a] + (S - sP[b]);
    float term = (m == spos) ? 0.f : (lo_s - __logf(denom));

    #pragma unroll
    for (int o = 16; o; o >>= 1) term += __shfl_xor_sync(0xffffffffu, term, o);
    __syncthreads();
    if (lane == 0) warpS[w] = term;
    __syncthreads();
    if (m == 0) {
        float s = 0.f;
        #pragma unroll
        for (int qq = 0; qq < 16; qq++) s += warpS[qq];
        atomicAdd(&g_acc, (double)s);
        __threadfence();
        int done = atomicAdd(&g_count, 1);
        if (done == N_TOT - 1) {
            double total = atomicAdd(&g_acc, 0.0);
            out[0] = (float)(-total / (double)(N_TOT * (N_TOT - 1)));
        }
    }
}

extern "C" void kernel_launch(void* const* d_in, const int* in_sizes, int n_in,
                              void* d_out, int out_size) {
    const float* wt = (const float*)d_in[0];
    const float* mt = (const float*)d_in[1];
    const float* lw = (const float*)d_in[2];
    const float* lm = (const float*)d_in[3];
    float* out = (float*)d_out;

    gemm_sort_kernel<<<GRID_G, 256>>>(wt, mt, lw, lm);
    loss_kernel<<<N_TOT, N_TOT>>>(lw, lm, out);
}